// round 13
// baseline (speedup 1.0000x reference)
#include <cuda_runtime.h>
#include <cstdint>

// ---------------------------------------------------------------------------
// SphericalExpansion, round 13: adjacent-pair ownership + red.v2 (halve REDs),
// f32x2 math packed across the lm-pair (per edge).
//
// Lane L (q=L&7, n0=L>>3) owns floats {n0*16+2q, +1, (n0+4)*16+2q, +1}:
//   RED1 across warp covers segment bytes [0,256), RED2 [256,512) -> same
//   traffic as before with HALF the RED instructions.
// Per edge: 1 MUFU exp (own rb, fc folded in), 4 shfl rb gathers,
//   packed-lm Y via cA-selects (f1) + 6 packed cF2 coeffs (f2),
//   2x red.global.add.v2.f32.
// 4-edge batch loads (float4/int4), branchless cutoff, adaptive grid.
// ---------------------------------------------------------------------------

typedef unsigned long long u64;

// f1 selector: 0 = 1, 1 = x, 2 = y, 3 = z
__constant__ int cFS[16] = {0,2,3,1, 0,0,0,0, 0,2,1,2, 3,1,3,1};
// f2 = c0 + cx*x2 + cz*z2 + cxy*xy + cyz*yz + czx*zx  (y^2 removed, verified)
__constant__ float cF2[16][6] = {
    { 0.28209479177387814f, 0,0, 0,0,0},
    { 0.4886025119029199f,  0,0, 0,0,0},
    { 0.4886025119029199f,  0,0, 0,0,0},
    { 0.4886025119029199f,  0,0, 0,0,0},
    { 0, 0,0, 1.0925484305920792f,0,0},
    { 0, 0,0, 0,1.0925484305920792f,0},
    {-0.31539156525252005f, 0.0f,               0.9461746957575602f, 0,0,0},
    { 0, 0,0, 0,0,1.0925484305920792f},
    {-0.5462742152960396f,  1.0925484305920792f,0.5462742152960396f, 0,0,0},
    {-0.5900435899266435f,  2.360174359706574f, 0.5900435899266435f, 0,0,0},
    { 0, 0,0, 0,2.890611442640554f,0},
    {-0.4570457994644658f,  0.0f,               2.285228997322329f,  0,0,0},
    {-1.1195289977703462f,  0.0f,               1.865881662950577f,  0,0,0},
    {-0.4570457994644658f,  0.0f,               2.285228997322329f,  0,0,0},
    {-1.445305721320277f,   2.890611442640554f, 1.445305721320277f,  0,0,0},
    {-1.7701307697799304f,  2.360174359706574f, 1.7701307697799304f, 0,0,0},
};
__constant__ int cLM2L[16] = {0,1,1,1, 2,2,2,2, 2,3,3,3, 3,3,3,3};

#define K2E (-2.8853900817779268f)   // -2*log2(e)

// ---- packed f32x2 helpers ----
__device__ __forceinline__ u64 pk2(float lo, float hi) {
    u64 r; asm("mov.b64 %0, {%1, %2};" : "=l"(r) : "f"(lo), "f"(hi)); return r;
}
__device__ __forceinline__ void upk2(float& lo, float& hi, u64 v) {
    asm("mov.b64 {%0, %1}, %2;" : "=f"(lo), "=f"(hi) : "l"(v));
}
__device__ __forceinline__ u64 mul2(u64 a, u64 b) {
    u64 r; asm("mul.rn.f32x2 %0, %1, %2;" : "=l"(r) : "l"(a), "l"(b)); return r;
}
__device__ __forceinline__ u64 fma2(u64 a, u64 b, u64 c) {
    u64 r; asm("fma.rn.f32x2 %0, %1, %2, %3;" : "=l"(r) : "l"(a), "l"(b), "l"(c)); return r;
}
__device__ __forceinline__ float ex2(float a) {
    float r; asm("ex2.approx.f32 %0, %1;" : "=f"(r) : "f"(a)); return r;
}
__device__ __forceinline__ float cutoff(float r) {
    const float u = __saturatef(fmaf(r, 2.0f, -9.0f));
    return fmaf(cospif(u), 0.5f, 0.5f);
}
__device__ __forceinline__ void red_v2(float* p, float a, float b) {
    asm volatile("red.global.add.v2.f32 [%0], {%1,%2};"
                 :: "l"(p), "f"(a), "f"(b) : "memory");
}

__global__ void __launch_bounds__(256) zero_out_kernel(float4* out, int n4) {
    int i = blockIdx.x * blockDim.x + threadIdx.x;
    int stride = gridDim.x * blockDim.x;
    float4 zv = make_float4(0.f, 0.f, 0.f, 0.f);
    for (; i < n4; i += stride) out[i] = zv;
}

__global__ void __launch_bounds__(256) sph_expand_kernel(
    const float* __restrict__ dist,
    const float* __restrict__ dirs,      // [J,3]
    const float* __restrict__ centers,   // [32]
    const int*   __restrict__ zspec,     // [N_ATOMS]
    const int*   __restrict__ idx_i,     // [J]
    const int*   __restrict__ idx_j,     // [J]
    float*       __restrict__ out,       // [N_ATOMS*4*8*16]
    int J)
{
    const int lane  = threadIdx.x & 31;
    const int warp  = (blockIdx.x * blockDim.x + threadIdx.x) >> 5;
    const int nwarp = (gridDim.x * blockDim.x) >> 5;

    const int q   = lane & 7;            // lm pair index: lm0=2q, lm1=2q+1
    const int n0  = lane >> 3;           // owned n (and n0+4)
    const int lm0 = 2*q, lm1 = 2*q + 1;
    const int l0  = cLM2L[lm0], l1 = cLM2L[lm1];

    // rb shuffle sources: rb[l][n] computed by lane 8*l+n
    const int sE0 = 8*l0 + n0;
    const int sO0 = 8*l1 + n0;
    const int sE4 = sE0 + 4;
    const int sO4 = sO0 + 4;

    // f1 selectors (predicates)
    const int fs0 = cFS[lm0], fs1 = cFS[lm1];
    const bool a_one = (fs0 == 0), a_x = (fs0 == 1), a_y = (fs0 == 2);
    const bool b_one = (fs1 == 0), b_x = (fs1 == 1), b_y = (fs1 == 2);

    // packed f2 coefficients for the lm pair (6 u64)
    const u64 C0  = pk2(cF2[lm0][0], cF2[lm1][0]);
    const u64 CX  = pk2(cF2[lm0][1], cF2[lm1][1]);
    const u64 CZ  = pk2(cF2[lm0][2], cF2[lm1][2]);
    const u64 CXY = pk2(cF2[lm0][3], cF2[lm1][3]);
    const u64 CYZ = pk2(cF2[lm0][4], cF2[lm1][4]);
    const u64 CZX = pk2(cF2[lm0][5], cF2[lm1][5]);

    const float cen = centers[lane];     // this lane computes rb[k=lane]

    // owned float offsets within the 128-float segment block
    float* const outLane = out + (n0 * 16 + 2 * q);
    const unsigned msk = 0xffffffffu;

    const int npacks = J >> 2;
    const float4* __restrict__ dist4 = (const float4*)dist;
    const float4* __restrict__ dirs4 = (const float4*)dirs;
    const int4*   __restrict__ ii4p  = (const int4*)idx_i;
    const int4*   __restrict__ jj4p  = (const int4*)idx_j;

    for (int pk = warp; pk < npacks; pk += nwarp) {
        // ---- batch loads: 4 edges, 10 LDGs (MLP=4 zspec chain) ----
        const float4 r4 = __ldg(dist4 + pk);
        const float4 d0 = __ldg(dirs4 + 3*pk + 0);
        const float4 d1 = __ldg(dirs4 + 3*pk + 1);
        const float4 d2 = __ldg(dirs4 + 3*pk + 2);
        const int4   i4 = __ldg(ii4p + pk);
        const int4   j4 = __ldg(jj4p + pk);

        int seg[4];
        seg[0] = (i4.x << 2) + __ldg(zspec + j4.x);
        seg[1] = (i4.y << 2) + __ldg(zspec + j4.y);
        seg[2] = (i4.z << 2) + __ldg(zspec + j4.z);
        seg[3] = (i4.w << 2) + __ldg(zspec + j4.w);

        const float rr[4] = {r4.x, r4.y, r4.z, r4.w};
        const float xx[4] = {d0.x, d0.w, d1.z, d2.y};
        const float yy[4] = {d0.y, d1.x, d1.w, d2.z};
        const float zv[4] = {d0.z, d1.y, d2.x, d2.w};

        #pragma unroll
        for (int k = 0; k < 4; k++) {
            const float r = rr[k], x = xx[k], y = yy[k], z = zv[k];

            // rb for this lane's center, cutoff folded in (pre-shuffle)
            const float t  = r - cen;
            const float rb = ex2(K2E * t * t) * cutoff(r);

            // packed-lm Y
            const u64 XX = pk2(x, x);
            const u64 YY = pk2(y, y);
            const u64 ZZ = pk2(z, z);
            const u64 f2 = fma2(CX, mul2(XX, XX),
                           fma2(CZ, mul2(ZZ, ZZ),
                           fma2(CXY, mul2(XX, YY),
                           fma2(CYZ, mul2(YY, ZZ),
                           fma2(CZX, mul2(ZZ, XX), C0)))));
            const float f1a = a_one ? 1.0f : (a_x ? x : (a_y ? y : z));
            const float f1b = b_one ? 1.0f : (b_x ? x : (b_y ? y : z));
            const u64 Yp = mul2(pk2(f1a, f1b), f2);

            // gather rb values for (l0,n0),(l1,n0),(l0,n0+4),(l1,n0+4)
            const float rE0 = __shfl_sync(msk, rb, sE0);
            const float rO0 = __shfl_sync(msk, rb, sO0);
            const float rE4 = __shfl_sync(msk, rb, sE4);
            const float rO4 = __shfl_sync(msk, rb, sO4);

            float v0a, v0b, v4a, v4b;
            upk2(v0a, v0b, mul2(Yp, pk2(rE0, rO0)));
            upk2(v4a, v4b, mul2(Yp, pk2(rE4, rO4)));

            float* p = outLane + ((size_t)(unsigned)seg[k] << 7);
            red_v2(p,      v0a, v0b);
            red_v2(p + 64, v4a, v4b);
        }
    }

    // tail (J not a multiple of 4) — cold scalar path
    for (int e = (npacks << 2) + warp; e < J; e += nwarp) {
        const float r = __ldg(dist + e);
        const float x = __ldg(dirs + 3*e + 0);
        const float y = __ldg(dirs + 3*e + 1);
        const float z = __ldg(dirs + 3*e + 2);
        const int  ii = __ldg(idx_i + e);
        const int  zj = __ldg(zspec + __ldg(idx_j + e));

        const float t  = r - cen;
        const float rb = ex2(K2E * t * t) * cutoff(r);

        const u64 XX = pk2(x, x);
        const u64 YY = pk2(y, y);
        const u64 ZZ = pk2(z, z);
        const u64 f2 = fma2(CX, mul2(XX, XX),
                       fma2(CZ, mul2(ZZ, ZZ),
                       fma2(CXY, mul2(XX, YY),
                       fma2(CYZ, mul2(YY, ZZ),
                       fma2(CZX, mul2(ZZ, XX), C0)))));
        const float f1a = a_one ? 1.0f : (a_x ? x : (a_y ? y : z));
        const float f1b = b_one ? 1.0f : (b_x ? x : (b_y ? y : z));
        const u64 Yp = mul2(pk2(f1a, f1b), f2);

        const float rE0 = __shfl_sync(msk, rb, sE0);
        const float rO0 = __shfl_sync(msk, rb, sO0);
        const float rE4 = __shfl_sync(msk, rb, sE4);
        const float rO4 = __shfl_sync(msk, rb, sO4);

        float v0a, v0b, v4a, v4b;
        upk2(v0a, v0b, mul2(Yp, pk2(rE0, rO0)));
        upk2(v4a, v4b, mul2(Yp, pk2(rE4, rO4)));

        float* p = outLane + ((size_t)(unsigned)(((ii << 2) + zj)) << 7);
        red_v2(p,      v0a, v0b);
        red_v2(p + 64, v4a, v4b);
    }
}

extern "C" void kernel_launch(void* const* d_in, const int* in_sizes, int n_in,
                              void* d_out, int out_size) {
    const float* dist    = (const float*)d_in[0];
    const float* dirs    = (const float*)d_in[1];
    const float* centers = (const float*)d_in[2];
    const int*   zspec   = (const int*)d_in[3];
    const int*   idx_i   = (const int*)d_in[4];
    const int*   idx_j   = (const int*)d_in[5];
    float*       out     = (float*)d_out;
    const int J = in_sizes[0];

    const int n4 = out_size / 4;
    zero_out_kernel<<<1184, 256>>>((float4*)d_out, n4);

    // Grid = one resident wave at the kernel's ACTUAL occupancy.
    int nsm = 148, occ = 4;
    cudaDeviceGetAttribute(&nsm, cudaDevAttrMultiProcessorCount, 0);
    cudaOccupancyMaxActiveBlocksPerMultiprocessor(&occ, sph_expand_kernel, 256, 0);
    if (occ < 1) occ = 1;
    sph_expand_kernel<<<nsm * occ, 256>>>(dist, dirs, centers, zspec,
                                          idx_i, idx_j, out, J);
}